// round 15
// baseline (speedup 1.0000x reference)
#include <cuda_runtime.h>
#include <cuda_bf16.h>
#include <cstdint>
#include <math.h>

// ---------------- problem constants ----------------------------------------
#define ZDIM 256
#define HID  128
#define NL   6
#define BB   2
#define IMG  64
#define HW   (IMG*IMG)          // 4096
#define SS   12
#define NRAYS (BB*HW)           // 8192
#define NPTS  (NRAYS*SS)        // 98304
#define FP_DIM (NL*HID)         // 768
#define MT    64                // points per block
#define NTHR  128               // 4 warps

#define ZC (-9.514364454222587f)

// weight tile: n-major (row = n, 128 k bf16 + pad), stride 272B
#define WROW  272
#define BSPL  (128*WROW)        // 34816 bytes per split
#define BBUF  (2*BSPL)          // 69632 bytes per layer (2 splits)

// prep kernel block partition
#define PREP_RAY_BLKS 384       // NPTS/256
#define PREP_WSP_BLKS 320       // 5*128*128/256
#define PREP_MAP_BLKS 24        // 2 batches x 12 column-blocks
#define PREP_BLKS (PREP_RAY_BLKS + PREP_WSP_BLKS + PREP_MAP_BLKS)

// ---------------- smem layout (bytes) — single B buffer, ~83KB/CTA ----------
#define SM_B    0               // BBUF = 69632 (B0 @0, B1 @BSPL)
#define SM_PTS  69632           // 192 floats
#define SM_FR   70400           // 768 floats
#define SM_PH   73472           // 768 floats
#define SM_BI   76544           // 640 floats
#define SM_FW   79104           // 384 floats
#define SM_FB   80640           // 128 floats
#define SM_OW   81152           // 512 floats
#define SM_OB   83200           // 4 floats
#define SM_TOTAL 83216

// ---------------- PTX helpers -----------------------------------------------
__device__ __forceinline__ uint32_t smem_u32(const void* p) {
    uint32_t a;
    asm("{ .reg .u64 t; cvta.to.shared.u64 t, %1; cvt.u32.u64 %0, t; }"
        : "=r"(a) : "l"(p));
    return a;
}
__device__ __forceinline__ void cp16(void* smem, const void* gmem) {
    uint32_t s = (uint32_t)__cvta_generic_to_shared(smem);
    asm volatile("cp.async.cg.shared.global [%0], [%1], 16;" :: "r"(s), "l"(gmem));
}
#define CP_COMMIT() asm volatile("cp.async.commit_group;")
#define CP_WAIT0()  asm volatile("cp.async.wait_group 0;")
#define CP_WAIT1()  asm volatile("cp.async.wait_group 1;")

#define LDMX4(r0, r1, r2, r3, addr) \
    asm volatile("ldmatrix.sync.aligned.m8n8.x4.shared.b16 {%0,%1,%2,%3}, [%4];" \
        : "=r"(r0), "=r"(r1), "=r"(r2), "=r"(r3) : "r"(addr))

#define MMA4(c, a0, a1, a2, a3, b0, b1) \
    asm volatile("mma.sync.aligned.m16n8k16.row.col.f32.bf16.bf16.f32 " \
        "{%0,%1,%2,%3}, {%4,%5,%6,%7}, {%8,%9}, {%0,%1,%2,%3};" \
        : "+f"((c)[0]), "+f"((c)[1]), "+f"((c)[2]), "+f"((c)[3]) \
        : "r"(a0), "r"(a1), "r"(a2), "r"(a3), "r"(b0), "r"(b1))

// ---------------- fast branch-free sin (verified round 6) -------------------
__device__ __forceinline__ float fast_sin(float x) {
    const float INVPI = 0.3183098861837907f;
    float fn = rintf(x * INVPI);
    int n = (int)fn;
    float r = fmaf(fn, -3.140625f, x);
    r = fmaf(fn, -9.67502593994140625e-4f, r);
    r = fmaf(fn, -1.50995799097838e-7f, r);
    float s = r * r;
    float p = fmaf(s, -1.9515295891e-4f, 8.3321608736e-3f);
    p = fmaf(s, p, -1.6666654611e-1f);
    float y = fmaf(r * s, p, r);
    return (n & 1) ? -y : y;
}

// 2-way bf16 split of a float pair, packed for mma A operands (lo = even k)
__device__ __forceinline__ void pack2(float x, float y,
                                      uint32_t& p0, uint32_t& p1) {
    __nv_bfloat162 h0 = __floats2bfloat162_rn(x, y);
    float2 g0 = __bfloat1622float2(h0);
    __nv_bfloat162 h1 = __floats2bfloat162_rn(x - g0.x, y - g0.y);
    p0 = *reinterpret_cast<uint32_t*>(&h0);
    p1 = *reinterpret_cast<uint32_t*>(&h1);
}

// ---------------- device scratch ---------------------------------------------
__device__ float g_freqs[BB*FP_DIM];
__device__ float g_phases[BB*FP_DIM];
__device__ float g_points[NPTS*3];
__device__ float g_zvals[NPTS];
__device__ float g_dirs[NRAYS*3];
__device__ float g_rgbs_c[NPTS*4];
__device__ float g_finez[NPTS];
__device__ float g_rgbs_f[NPTS*4];
// pre-split hidden weights: 5 layers x (2 splits x 128 n-rows x 272B)
__device__ __align__(16) char g_wsplit[5*BBUF];

// ---------------- Threefry-2x32-20 (matches JAX) ----------------------------
__host__ __device__ static inline void tf2x32(uint32_t k0, uint32_t k1,
                                              uint32_t& x0, uint32_t& x1) {
    uint32_t ks2 = k0 ^ k1 ^ 0x1BD11BDAu;
    x0 += k0; x1 += k1;
#define TF_RND(r) { x0 += x1; x1 = (x1 << (r)) | (x1 >> (32 - (r))); x1 ^= x0; }
    TF_RND(13) TF_RND(15) TF_RND(26) TF_RND(6)
    x0 += k1;  x1 += ks2 + 1u;
    TF_RND(17) TF_RND(29) TF_RND(16) TF_RND(24)
    x0 += ks2; x1 += k0 + 2u;
    TF_RND(13) TF_RND(15) TF_RND(26) TF_RND(6)
    x0 += k0;  x1 += k1 + 3u;
    TF_RND(17) TF_RND(29) TF_RND(16) TF_RND(24)
    x0 += k1;  x1 += ks2 + 4u;
    TF_RND(13) TF_RND(15) TF_RND(26) TF_RND(6)
    x0 += ks2; x1 += k0 + 5u;
#undef TF_RND
}
__device__ static inline float jax_uniform(uint32_t k0, uint32_t k1, uint32_t idx) {
    uint32_t x0 = 0u, x1 = idx;
    tf2x32(k0, k1, x0, x1);
    uint32_t bits = x0 ^ x1;
    return __uint_as_float((bits >> 9) | 0x3f800000u) - 1.0f;
}

// ---------------- kernel 0: fused prep (raygen + wsplit + mapping) ----------
__global__ void prep_kernel(const float* __restrict__ z,
                            const float* __restrict__ c2w,
                            const float* __restrict__ w0, const float* __restrict__ b0,
                            const float* __restrict__ w1, const float* __restrict__ b1,
                            const float* __restrict__ w2, const float* __restrict__ b2,
                            const float* __restrict__ hw_,
                            uint32_t kp0, uint32_t kp1) {
    __shared__ float sh[ZDIM];
    int blk = blockIdx.x, t = threadIdx.x;

    if (blk < PREP_RAY_BLKS) {
        int gid = blk*256 + t;           // == ray*SS + s
        int ray = gid / SS, s = gid % SS;
        int b = ray / HW, r = ray % HW;
        int h = r / IMG, w = r % IMG;
        float x = -1.0f + w * (2.0f/63.0f);
        float y =  1.0f - h * (2.0f/63.0f);
        float n  = sqrtf(x*x + y*y + ZC*ZC);
        float dx = x/n, dy = y/n, dz = ZC/n;
        const float* M = c2w + b*16;
        if (s == 0) {
            g_dirs[ray*3+0] = M[0]*dx + M[1]*dy + M[2]*dz;
            g_dirs[ray*3+1] = M[4]*dx + M[5]*dy + M[6]*dz;
            g_dirs[ray*3+2] = M[8]*dx + M[9]*dy + M[10]*dz;
        }
        const float spacing = (1.12f - 0.88f) / 11.0f;
        float u   = jax_uniform(kp0, kp1, (uint32_t)gid);
        float off = (u - 0.5f) * spacing;
        float zv  = 0.88f + s*spacing + off;
        float px = dx*zv, py = dy*zv, pz = dz*zv;
        g_points[gid*3+0] = M[0]*px + M[1]*py + M[2]*pz  + M[3];
        g_points[gid*3+1] = M[4]*px + M[5]*py + M[6]*pz  + M[7];
        g_points[gid*3+2] = M[8]*px + M[9]*py + M[10]*pz + M[11];
        g_zvals[gid] = zv;
    } else if (blk < PREP_RAY_BLKS + PREP_WSP_BLKS) {
        int idx = (blk - PREP_RAY_BLKS)*256 + t;   // < 5*128*128
        int l = idx / (HID*HID), r = idx % (HID*HID);
        int k = r >> 7, n = r & 127;
        float w = hw_[l*HID*HID + k*HID + n];
        __nv_bfloat16 h0 = __float2bfloat16(w);
        float r1 = w - __bfloat162float(h0);
        __nv_bfloat16 h1 = __float2bfloat16(r1);
        int off = n*WROW + k*2;
        char* base = g_wsplit + l*BBUF;
        *(__nv_bfloat16*)(base + off)        = h0;
        *(__nv_bfloat16*)(base + BSPL + off) = h1;
    } else {
        int mb = blk - (PREP_RAY_BLKS + PREP_WSP_BLKS);  // 0..23
        int batch = mb / 12, cb = mb % 12;
        sh[t] = z[batch*ZDIM + t];
        __syncthreads();
        float acc = b0[t];
        for (int k = 0; k < ZDIM; k++) acc = fmaf(sh[k], w0[k*256 + t], acc);
        float v = (acc >= 0.f) ? acc : 0.2f*acc;
        __syncthreads(); sh[t] = v; __syncthreads();
        acc = b1[t];
        for (int k = 0; k < 256; k++) acc = fmaf(sh[k], w1[k*256 + t], acc);
        v = (acc >= 0.f) ? acc : 0.2f*acc;
        __syncthreads(); sh[t] = v; __syncthreads();
        if (t < 128) {
            int j = cb*128 + t;                     // covers [0,1536)
            float a = b2[j];
            for (int k = 0; k < 256; k++) a = fmaf(sh[k], w2[k*(FP_DIM*2) + j], a);
            if (j < FP_DIM) g_freqs[batch*FP_DIM + j] = a*15.0f + 30.0f;
            else            g_phases[batch*FP_DIM + (j - FP_DIM)] = a;
        }
    }
}

// ---------------- kernel: HMMA fused SIREN, split-pipelined staging ---------
// 128 threads = 4 warps, MT=64, 2 CTAs/SM. Per layer:
//   phase A: MMA combos A0B0+A1B0 (reads only B0); BAR; prefetch next B0
//   wait B1 + BAR; phase B: combo A0B1 (reads only B1); BAR; prefetch next B1
//   epilogue (regs only; overlaps both prefetches); wait(<=1) + BAR
// Staging is thus hidden under MMA/epilogue instead of exposed post-barrier.
// Fine pass computes its own inverse-CDF sample points in the prologue.
__global__ void __launch_bounds__(NTHR, 2)
siren_mma_kernel(int fine, const float* __restrict__ c2w,
                 const float* __restrict__ fw, const float* __restrict__ fb,
                 const float* __restrict__ hb,
                 const float* __restrict__ ow, const float* __restrict__ ob,
                 uint32_t kq0, uint32_t kq1) {
    extern __shared__ char smc[];
    uint32_t smb = smem_u32(smc);
    float* ptss = (float*)(smc + SM_PTS);
    float* frs  = (float*)(smc + SM_FR);
    float* phs  = (float*)(smc + SM_PH);
    float* bis  = (float*)(smc + SM_BI);
    float* fws  = (float*)(smc + SM_FW);
    float* fbs  = (float*)(smc + SM_FB);
    float* ows  = (float*)(smc + SM_OW);
    float* obs  = (float*)(smc + SM_OB);

    float* outr = fine ? g_rgbs_f : g_rgbs_c;

    int tid = threadIdx.x;
    int wid = tid >> 5, lane = tid & 31;
    int m0 = blockIdx.x * MT;
    int batch = m0 / (HW*SS);

    // prefetch layer-1 weights: B0 group, then B1 group
    for (int i = tid; i < BSPL/16; i += NTHR)
        cp16(smc + SM_B + i*16, g_wsplit + i*16);
    CP_COMMIT();
    for (int i = tid; i < BSPL/16; i += NTHR)
        cp16(smc + SM_B + BSPL + i*16, g_wsplit + BSPL + i*16);
    CP_COMMIT();

    // stage constants + points
    {
        const float* frq = g_freqs  + batch*FP_DIM;
        const float* phq = g_phases + batch*FP_DIM;
        for (int i = tid; i < FP_DIM; i += NTHR) { frs[i] = frq[i]; phs[i] = phq[i]; }
        for (int i = tid; i < (NL-1)*HID; i += NTHR) bis[i] = hb[i];
        for (int i = tid; i < 384; i += NTHR) fws[i] = fw[i];
        if (tid < 128) fbs[tid] = fb[tid];
        for (int i = tid; i < 512; i += NTHR) ows[i] = ow[i];
        if (tid < 4) obs[tid] = ob[tid];

        if (!fine) {
            for (int i = tid; i < MT*3; i += NTHR) ptss[i] = g_points[m0*3 + i];
        } else if (tid < MT) {
            // fused inverse-CDF sampling (bit-identical to reference order)
            int gid = m0 + tid;
            int ray = gid / SS;
            int b = ray / HW;
            int base = ray * SS;
            float z[SS], sg[SS];
            for (int s = 0; s < SS; s++) {
                z[s]  = g_zvals[base + s];
                sg[s] = g_rgbs_c[(base + s)*4 + 3];
            }
            float wgt[SS]; float T = 1.0f;
            for (int s = 0; s < SS; s++) {
                float d = (s < SS-1) ? (z[s+1] - z[s]) : 1e10f;
                float a = 1.0f - expf(-d * fmaxf(sg[s], 0.0f));
                wgt[s] = a * T;
                T *= (1.0f - a + 1e-10f);
            }
            float wq[SS-2]; float sum = 0.0f;
            for (int i = 0; i < SS-2; i++) { wq[i] = wgt[i+1] + 1e-5f; sum += wq[i]; }
            float cdf[SS-1]; cdf[0] = 0.0f; float c = 0.0f;
            for (int i = 0; i < SS-2; i++) { c += wq[i] / sum; cdf[i+1] = c; }
            float bins[SS-1];
            for (int i = 0; i < SS-1; i++) bins[i] = 0.5f * (z[i] + z[i+1]);
            float ox = c2w[b*16 + 3], oy = c2w[b*16 + 7], oz = c2w[b*16 + 11];
            float dx = g_dirs[ray*3+0], dy = g_dirs[ray*3+1], dz = g_dirs[ray*3+2];
            float u = jax_uniform(kq0, kq1, (uint32_t)gid);
            int ind = SS-1;
            for (int i = 0; i < SS-1; i++) { if (cdf[i] > u) { ind = i; break; } }
            int below = ind - 1; if (below < 0) below = 0; if (below > SS-2) below = SS-2;
            int above = (ind > SS-2) ? (SS-2) : ind;
            float clo = cdf[below], chi = cdf[above];
            float blo = bins[below], bhi = bins[above];
            float den = chi - clo; if (den < 1e-8f) den = 1.0f;
            float fz = blo + (u - clo) / den * (bhi - blo);
            g_finez[gid] = fz;
            ptss[tid*3 + 0] = ox + dx*fz;
            ptss[tid*3 + 1] = oy + dy*fz;
            ptss[tid*3 + 2] = oz + dz*fz;
        }
    }
    __syncthreads();

    uint32_t A0[8][4], A1[8][4];

    // ---- first layer: 3 -> 128 scalar, directly into fragment layout ----
    {
        int rr = lane >> 2;
        int mr0 = wid*16 + rr, mr1 = mr0 + 8;
        float p00 = ptss[mr0*3], p01 = ptss[mr0*3+1], p02 = ptss[mr0*3+2];
        float p10 = ptss[mr1*3], p11 = ptss[mr1*3+1], p12 = ptss[mr1*3+2];
#pragma unroll
        for (int j = 0; j < 16; j++) {
            int n = 8*j + 2*(lane & 3);
            float wa0 = fws[n],   wa1 = fws[128+n],   wa2 = fws[256+n];
            float wb0 = fws[n+1], wb1 = fws[128+n+1], wb2 = fws[256+n+1];
            float ba = fbs[n], bbv = fbs[n+1];
            float fa = frs[n], fbq = frs[n+1], pa = phs[n], pb = phs[n+1];
            float v0 = fast_sin(fa *(ba  + p00*wa0 + p01*wa1 + p02*wa2) + pa);
            float v1 = fast_sin(fbq*(bbv + p00*wb0 + p01*wb1 + p02*wb2) + pb);
            float v2 = fast_sin(fa *(ba  + p10*wa0 + p11*wa1 + p12*wa2) + pa);
            float v3 = fast_sin(fbq*(bbv + p10*wb0 + p11*wb1 + p12*wb2) + pb);
            int s = j >> 1, i0 = (j & 1)*2;
            pack2(v0, v1, A0[s][i0],   A1[s][i0]);
            pack2(v2, v3, A0[s][i0+1], A1[s][i0+1]);
        }
    }
    CP_WAIT1();        // B0 of layer 1 ready (B1 may still be in flight)
    __syncthreads();

    int tile = lane >> 3;
    uint32_t rowoff = (uint32_t)((((tile >> 1)*8 + (lane & 7))*WROW) + (tile & 1)*16);

#pragma unroll 1
    for (int l = 1; l < NL; l++) {
        uint32_t bbase = smb + SM_B;
        float acc[16][4];
#pragma unroll
        for (int j = 0; j < 16; j++)
#pragma unroll
            for (int e = 0; e < 4; e++) acc[j][e] = 0.f;

        // ---- phase A: combos A0B0 + A1B0 (reads only B0) ----
#pragma unroll
        for (int s = 0; s < 8; s++) {
            uint32_t ad0 = bbase + s*32 + rowoff;
#pragma unroll
            for (int jq = 0; jq < 4; jq++) {
                uint32_t t0, t1, t2, t3, u0, u1, u2, u3;
                LDMX4(t0, t1, t2, t3, ad0 + (2*jq)  *(16*WROW));
                LDMX4(u0, u1, u2, u3, ad0 + (2*jq+1)*(16*WROW));
                float* c0 = acc[4*jq];
                float* c1 = acc[4*jq+1];
                float* c2 = acc[4*jq+2];
                float* c3 = acc[4*jq+3];
                MMA4(c0, A0[s][0], A0[s][1], A0[s][2], A0[s][3], t0, t1);
                MMA4(c1, A0[s][0], A0[s][1], A0[s][2], A0[s][3], t2, t3);
                MMA4(c2, A0[s][0], A0[s][1], A0[s][2], A0[s][3], u0, u1);
                MMA4(c3, A0[s][0], A0[s][1], A0[s][2], A0[s][3], u2, u3);
                MMA4(c0, A1[s][0], A1[s][1], A1[s][2], A1[s][3], t0, t1);
                MMA4(c1, A1[s][0], A1[s][1], A1[s][2], A1[s][3], t2, t3);
                MMA4(c2, A1[s][0], A1[s][1], A1[s][2], A1[s][3], u0, u1);
                MMA4(c3, A1[s][0], A1[s][1], A1[s][2], A1[s][3], u2, u3);
            }
        }
        __syncthreads();   // all warps done reading B0(l)

        // prefetch next layer's B0 (overlaps phase B + epilogue)
        if (l < NL-1) {
            const char* src = g_wsplit + l*BBUF;
            for (int i = tid; i < BSPL/16; i += NTHR)
                cp16(smc + SM_B + i*16, src + i*16);
            CP_COMMIT();
            CP_WAIT1();    // B1(l) ready (next-B0 group may be outstanding)
        } else {
            CP_WAIT0();    // B1(NL-1) ready
        }
        __syncthreads();

        // ---- phase B: combo A0B1 (reads only B1) ----
#pragma unroll
        for (int s = 0; s < 8; s++) {
            uint32_t ad1 = bbase + BSPL + s*32 + rowoff;
#pragma unroll
            for (int jq = 0; jq < 4; jq++) {
                uint32_t v0, v1, v2, v3, w0, w1, w2, w3;
                LDMX4(v0, v1, v2, v3, ad1 + (2*jq)  *(16*WROW));
                LDMX4(w0, w1, w2, w3, ad1 + (2*jq+1)*(16*WROW));
                float* c0 = acc[4*jq];
                float* c1 = acc[4*jq+1];
                float* c2 = acc[4*jq+2];
                float* c3 = acc[4*jq+3];
                MMA4(c0, A0[s][0], A0[s][1], A0[s][2], A0[s][3], v0, v1);
                MMA4(c1, A0[s][0], A0[s][1], A0[s][2], A0[s][3], v2, v3);
                MMA4(c2, A0[s][0], A0[s][1], A0[s][2], A0[s][3], w0, w1);
                MMA4(c3, A0[s][0], A0[s][1], A0[s][2], A0[s][3], w2, w3);
            }
        }
        __syncthreads();   // all warps done reading B1(l)

        // prefetch next layer's B1 (overlaps epilogue + next phase A)
        if (l < NL-1) {
            const char* src = g_wsplit + l*BBUF + BSPL;
            for (int i = tid; i < BSPL/16; i += NTHR)
                cp16(smc + SM_B + BSPL + i*16, src + i*16);
            CP_COMMIT();
        }

        if (l < NL-1) {
            // epilogue: sin + split into A fragments (regs only)
#pragma unroll
            for (int j = 0; j < 16; j++) {
                int n = 8*j + 2*(lane & 3);
                float2 f  = *(const float2*)&frs[l*HID + n];
                float2 p  = *(const float2*)&phs[l*HID + n];
                float2 bb = *(const float2*)&bis[(l-1)*HID + n];
                float v0 = fast_sin(f.x*(acc[j][0] + bb.x) + p.x);
                float v1 = fast_sin(f.y*(acc[j][1] + bb.y) + p.y);
                float v2 = fast_sin(f.x*(acc[j][2] + bb.x) + p.x);
                float v3 = fast_sin(f.y*(acc[j][3] + bb.y) + p.y);
                int s = j >> 1, i0 = (j & 1)*2;
                pack2(v0, v1, A0[s][i0],   A1[s][i0]);
                pack2(v2, v3, A0[s][i0+1], A1[s][i0+1]);
            }
            // wait: next-B0 ready (next-B1 group may remain outstanding)
            CP_WAIT1();
            __syncthreads();
        } else {
            // final epilogue: sin then fused 128->4 output projection
            float o0[4] = {0.f, 0.f, 0.f, 0.f};
            float o1[4] = {0.f, 0.f, 0.f, 0.f};
#pragma unroll
            for (int j = 0; j < 16; j++) {
                int n = 8*j + 2*(lane & 3);
                float2 f  = *(const float2*)&frs[l*HID + n];
                float2 p  = *(const float2*)&phs[l*HID + n];
                float2 bb = *(const float2*)&bis[(l-1)*HID + n];
                float v0 = fast_sin(f.x*(acc[j][0] + bb.x) + p.x);
                float v1 = fast_sin(f.y*(acc[j][1] + bb.y) + p.y);
                float v2 = fast_sin(f.x*(acc[j][2] + bb.x) + p.x);
                float v3 = fast_sin(f.y*(acc[j][3] + bb.y) + p.y);
                float4 wA = *(const float4*)&ows[n*4];
                float4 wB = *(const float4*)&ows[(n+1)*4];
                o0[0] = fmaf(v0, wA.x, fmaf(v1, wB.x, o0[0]));
                o0[1] = fmaf(v0, wA.y, fmaf(v1, wB.y, o0[1]));
                o0[2] = fmaf(v0, wA.z, fmaf(v1, wB.z, o0[2]));
                o0[3] = fmaf(v0, wA.w, fmaf(v1, wB.w, o0[3]));
                o1[0] = fmaf(v2, wA.x, fmaf(v3, wB.x, o1[0]));
                o1[1] = fmaf(v2, wA.y, fmaf(v3, wB.y, o1[1]));
                o1[2] = fmaf(v2, wA.z, fmaf(v3, wB.z, o1[2]));
                o1[3] = fmaf(v2, wA.w, fmaf(v3, wB.w, o1[3]));
            }
#pragma unroll
            for (int off = 1; off <= 2; off <<= 1) {
#pragma unroll
                for (int q = 0; q < 4; q++) {
                    o0[q] += __shfl_xor_sync(0xffffffffu, o0[q], off);
                    o1[q] += __shfl_xor_sync(0xffffffffu, o1[q], off);
                }
            }
            if ((lane & 3) == 0) {
                int rr = lane >> 2;
                int row0 = m0 + wid*16 + rr, row1 = row0 + 8;
                float a0 = o0[0] + obs[0], a1 = o0[1] + obs[1];
                float a2 = o0[2] + obs[2], a3 = o0[3] + obs[3];
                float b0 = o1[0] + obs[0], b1 = o1[1] + obs[1];
                float b2 = o1[2] + obs[2], b3 = o1[3] + obs[3];
                float4 q0 = make_float4(1.f/(1.f+expf(-a0)), 1.f/(1.f+expf(-a1)),
                                        1.f/(1.f+expf(-a2)), a3);
                float4 q1 = make_float4(1.f/(1.f+expf(-b0)), 1.f/(1.f+expf(-b1)),
                                        1.f/(1.f+expf(-b2)), b3);
                *(float4*)&outr[row0*4] = q0;
                *(float4*)&outr[row1*4] = q1;
            }
        }
    }
}

// ---------------- kernel 6: merge-sort + final integration ------------------
__global__ void final_kernel(float* __restrict__ out) {
    int ray = blockIdx.x * blockDim.x + threadIdx.x;
    if (ray >= NRAYS) return;
    int b = ray / HW, r = ray % HW;
    int h = r / IMG, w = r % IMG;
    int base = ray * SS;

    float z[2*SS]; float4 c[2*SS];
    const float4* rf = reinterpret_cast<const float4*>(g_rgbs_f);
    const float4* rc = reinterpret_cast<const float4*>(g_rgbs_c);
    for (int s = 0; s < SS; s++) { z[s]    = g_finez[base+s]; c[s]    = rf[base+s]; }
    for (int s = 0; s < SS; s++) { z[SS+s] = g_zvals[base+s]; c[SS+s] = rc[base+s]; }

    for (int i = 1; i < 2*SS; i++) {
        float kz = z[i]; float4 kc = c[i];
        int j = i - 1;
        while (j >= 0 && z[j] > kz) { z[j+1] = z[j]; c[j+1] = c[j]; j--; }
        z[j+1] = kz; c[j+1] = kc;
    }

    float T = 1.0f, R = 0.f, G = 0.f, Bc = 0.f, D = 0.f;
    for (int s = 0; s < 2*SS; s++) {
        float d = (s < 2*SS-1) ? (z[s+1] - z[s]) : 1e10f;
        float a = 1.0f - expf(-d * fmaxf(c[s].w, 0.0f));
        float wt = a * T;
        T *= (1.0f - a + 1e-10f);
        R += wt * c[s].x; G += wt * c[s].y; Bc += wt * c[s].z; D += wt * z[s];
    }
    out[((b*3 + 0)*IMG + h)*IMG + w] = R  * 2.0f - 1.0f;
    out[((b*3 + 1)*IMG + h)*IMG + w] = G  * 2.0f - 1.0f;
    out[((b*3 + 2)*IMG + h)*IMG + w] = Bc * 2.0f - 1.0f;
    float x = -1.0f + w * (2.0f/63.0f);
    float y =  1.0f - h * (2.0f/63.0f);
    float n = sqrtf(x*x + y*y + ZC*ZC);
    out[BB*3*HW + ray] = D * (-(ZC/n));
}

// ---------------- launch ------------------------------------------------------
extern "C" void kernel_launch(void* const* d_in, const int* in_sizes, int n_in,
                              void* d_out, int out_size) {
    const float* z    = (const float*)d_in[0];
    const float* c2w  = (const float*)d_in[1];
    const float* mw0  = (const float*)d_in[2];
    const float* mb0  = (const float*)d_in[3];
    const float* mw1  = (const float*)d_in[4];
    const float* mb1  = (const float*)d_in[5];
    const float* mw2  = (const float*)d_in[6];
    const float* mb2  = (const float*)d_in[7];
    const float* fw   = (const float*)d_in[8];
    const float* fb   = (const float*)d_in[9];
    const float* hw_  = (const float*)d_in[10];
    const float* hb   = (const float*)d_in[11];
    const float* ow   = (const float*)d_in[12];
    const float* ob   = (const float*)d_in[13];
    float* out = (float*)d_out;

    uint32_t kp0, kp1, kq0, kq1;
    { uint32_t x0 = 0u, x1 = 0u; tf2x32(0u, 42u, x0, x1); kp0 = x0; kp1 = x1; }
    { uint32_t x0 = 0u, x1 = 1u; tf2x32(0u, 42u, x0, x1); kq0 = x0; kq1 = x1; }

    cudaFuncSetAttribute(siren_mma_kernel,
                         cudaFuncAttributeMaxDynamicSharedMemorySize, SM_TOTAL);

    prep_kernel<<<PREP_BLKS, 256>>>(z, c2w, mw0, mb0, mw1, mb1, mw2, mb2,
                                    hw_, kp0, kp1);
    siren_mma_kernel<<<NPTS/MT, NTHR, SM_TOTAL>>>(0, c2w, fw, fb, hb, ow, ob,
                                                  kq0, kq1);
    siren_mma_kernel<<<NPTS/MT, NTHR, SM_TOTAL>>>(1, c2w, fw, fb, hb, ow, ob,
                                                  kq0, kq1);
    final_kernel <<<NRAYS/256, 256>>>(out);
}

// round 16
// speedup vs baseline: 1.1205x; 1.1205x over previous
#include <cuda_runtime.h>
#include <cuda_bf16.h>
#include <cstdint>
#include <math.h>

// ---------------- problem constants ----------------------------------------
#define ZDIM 256
#define HID  128
#define NL   6
#define BB   2
#define IMG  64
#define HW   (IMG*IMG)          // 4096
#define SS   12
#define NRAYS (BB*HW)           // 8192
#define NPTS  (NRAYS*SS)        // 98304
#define FP_DIM (NL*HID)         // 768
#define MT    64                // points per block
#define NTHR  128               // 4 warps

#define ZC (-9.514364454222587f)

// weight tile: n-major (row = n, 128 k bf16 + pad), stride 272B
#define WROW  272
#define BSPL  (128*WROW)        // 34816 bytes per split
#define BBUF  (2*BSPL)          // 69632 bytes per layer (2 splits)

// prep kernel block partition
#define PREP_RAY_BLKS 384       // NPTS/256
#define PREP_WSP_BLKS 320       // 5*128*128/256
#define PREP_MAP_BLKS 24        // 2 batches x 12 column-blocks
#define PREP_BLKS (PREP_RAY_BLKS + PREP_WSP_BLKS + PREP_MAP_BLKS)

// ---------------- smem layout (bytes) — single B buffer, ~83KB/CTA ----------
#define SM_B    0               // BBUF = 69632
#define SM_PTS  69632           // 192 floats
#define SM_FR   70400           // 768 floats
#define SM_PH   73472           // 768 floats
#define SM_BI   76544           // 640 floats
#define SM_FW   79104           // 384 floats
#define SM_FB   80640           // 128 floats
#define SM_OW   81152           // 512 floats
#define SM_OB   83200           // 4 floats
#define SM_TOTAL 83216

// ---------------- PTX helpers -----------------------------------------------
__device__ __forceinline__ uint32_t smem_u32(const void* p) {
    uint32_t a;
    asm("{ .reg .u64 t; cvta.to.shared.u64 t, %1; cvt.u32.u64 %0, t; }"
        : "=r"(a) : "l"(p));
    return a;
}
__device__ __forceinline__ void cp16(void* smem, const void* gmem) {
    uint32_t s = (uint32_t)__cvta_generic_to_shared(smem);
    asm volatile("cp.async.cg.shared.global [%0], [%1], 16;" :: "r"(s), "l"(gmem));
}
#define CP_COMMIT() asm volatile("cp.async.commit_group;")
#define CP_WAIT0()  asm volatile("cp.async.wait_group 0;")

#define LDMX4(r0, r1, r2, r3, addr) \
    asm volatile("ldmatrix.sync.aligned.m8n8.x4.shared.b16 {%0,%1,%2,%3}, [%4];" \
        : "=r"(r0), "=r"(r1), "=r"(r2), "=r"(r3) : "r"(addr))

#define MMA4(c, a0, a1, a2, a3, b0, b1) \
    asm volatile("mma.sync.aligned.m16n8k16.row.col.f32.bf16.bf16.f32 " \
        "{%0,%1,%2,%3}, {%4,%5,%6,%7}, {%8,%9}, {%0,%1,%2,%3};" \
        : "+f"((c)[0]), "+f"((c)[1]), "+f"((c)[2]), "+f"((c)[3]) \
        : "r"(a0), "r"(a1), "r"(a2), "r"(a3), "r"(b0), "r"(b1))

// ---------------- fast branch-free sin (verified round 6) -------------------
__device__ __forceinline__ float fast_sin(float x) {
    const float INVPI = 0.3183098861837907f;
    float fn = rintf(x * INVPI);
    int n = (int)fn;
    float r = fmaf(fn, -3.140625f, x);
    r = fmaf(fn, -9.67502593994140625e-4f, r);
    r = fmaf(fn, -1.50995799097838e-7f, r);
    float s = r * r;
    float p = fmaf(s, -1.9515295891e-4f, 8.3321608736e-3f);
    p = fmaf(s, p, -1.6666654611e-1f);
    float y = fmaf(r * s, p, r);
    return (n & 1) ? -y : y;
}

// 2-way bf16 split of a float pair, packed for mma A operands (lo = even k)
__device__ __forceinline__ void pack2(float x, float y,
                                      uint32_t& p0, uint32_t& p1) {
    __nv_bfloat162 h0 = __floats2bfloat162_rn(x, y);
    float2 g0 = __bfloat1622float2(h0);
    __nv_bfloat162 h1 = __floats2bfloat162_rn(x - g0.x, y - g0.y);
    p0 = *reinterpret_cast<uint32_t*>(&h0);
    p1 = *reinterpret_cast<uint32_t*>(&h1);
}

// ---------------- device scratch ---------------------------------------------
__device__ float g_freqs[BB*FP_DIM];
__device__ float g_phases[BB*FP_DIM];
__device__ float g_points[NPTS*3];
__device__ float g_zvals[NPTS];
__device__ float g_dirs[NRAYS*3];
__device__ float g_rgbs_c[NPTS*4];
__device__ float g_finez[NPTS];
__device__ float g_points_f[NPTS*3];
__device__ float g_rgbs_f[NPTS*4];
// pre-split hidden weights: 5 layers x (2 splits x 128 n-rows x 272B)
__device__ __align__(16) char g_wsplit[5*BBUF];

// ---------------- Threefry-2x32-20 (matches JAX) ----------------------------
__host__ __device__ static inline void tf2x32(uint32_t k0, uint32_t k1,
                                              uint32_t& x0, uint32_t& x1) {
    uint32_t ks2 = k0 ^ k1 ^ 0x1BD11BDAu;
    x0 += k0; x1 += k1;
#define TF_RND(r) { x0 += x1; x1 = (x1 << (r)) | (x1 >> (32 - (r))); x1 ^= x0; }
    TF_RND(13) TF_RND(15) TF_RND(26) TF_RND(6)
    x0 += k1;  x1 += ks2 + 1u;
    TF_RND(17) TF_RND(29) TF_RND(16) TF_RND(24)
    x0 += ks2; x1 += k0 + 2u;
    TF_RND(13) TF_RND(15) TF_RND(26) TF_RND(6)
    x0 += k0;  x1 += k1 + 3u;
    TF_RND(17) TF_RND(29) TF_RND(16) TF_RND(24)
    x0 += k1;  x1 += ks2 + 4u;
    TF_RND(13) TF_RND(15) TF_RND(26) TF_RND(6)
    x0 += ks2; x1 += k0 + 5u;
#undef TF_RND
}
__device__ static inline float jax_uniform(uint32_t k0, uint32_t k1, uint32_t idx) {
    uint32_t x0 = 0u, x1 = idx;
    tf2x32(k0, k1, x0, x1);
    uint32_t bits = x0 ^ x1;
    return __uint_as_float((bits >> 9) | 0x3f800000u) - 1.0f;
}

// ---------------- kernel 0: fused prep (raygen + wsplit + mapping) ----------
__global__ void prep_kernel(const float* __restrict__ z,
                            const float* __restrict__ c2w,
                            const float* __restrict__ w0, const float* __restrict__ b0,
                            const float* __restrict__ w1, const float* __restrict__ b1,
                            const float* __restrict__ w2, const float* __restrict__ b2,
                            const float* __restrict__ hw_,
                            uint32_t kp0, uint32_t kp1) {
    __shared__ float sh[ZDIM];
    int blk = blockIdx.x, t = threadIdx.x;

    if (blk < PREP_RAY_BLKS) {
        int gid = blk*256 + t;           // == ray*SS + s
        int ray = gid / SS, s = gid % SS;
        int b = ray / HW, r = ray % HW;
        int h = r / IMG, w = r % IMG;
        float x = -1.0f + w * (2.0f/63.0f);
        float y =  1.0f - h * (2.0f/63.0f);
        float n  = sqrtf(x*x + y*y + ZC*ZC);
        float dx = x/n, dy = y/n, dz = ZC/n;
        const float* M = c2w + b*16;
        if (s == 0) {
            g_dirs[ray*3+0] = M[0]*dx + M[1]*dy + M[2]*dz;
            g_dirs[ray*3+1] = M[4]*dx + M[5]*dy + M[6]*dz;
            g_dirs[ray*3+2] = M[8]*dx + M[9]*dy + M[10]*dz;
        }
        const float spacing = (1.12f - 0.88f) / 11.0f;
        float u   = jax_uniform(kp0, kp1, (uint32_t)gid);
        float off = (u - 0.5f) * spacing;
        float zv  = 0.88f + s*spacing + off;
        float px = dx*zv, py = dy*zv, pz = dz*zv;
        g_points[gid*3+0] = M[0]*px + M[1]*py + M[2]*pz  + M[3];
        g_points[gid*3+1] = M[4]*px + M[5]*py + M[6]*pz  + M[7];
        g_points[gid*3+2] = M[8]*px + M[9]*py + M[10]*pz + M[11];
        g_zvals[gid] = zv;
    } else if (blk < PREP_RAY_BLKS + PREP_WSP_BLKS) {
        int idx = (blk - PREP_RAY_BLKS)*256 + t;   // < 5*128*128
        int l = idx / (HID*HID), r = idx % (HID*HID);
        int k = r >> 7, n = r & 127;
        float w = hw_[l*HID*HID + k*HID + n];
        __nv_bfloat16 h0 = __float2bfloat16(w);
        float r1 = w - __bfloat162float(h0);
        __nv_bfloat16 h1 = __float2bfloat16(r1);
        int off = n*WROW + k*2;
        char* base = g_wsplit + l*BBUF;
        *(__nv_bfloat16*)(base + off)        = h0;
        *(__nv_bfloat16*)(base + BSPL + off) = h1;
    } else {
        int mb = blk - (PREP_RAY_BLKS + PREP_WSP_BLKS);  // 0..23
        int batch = mb / 12, cb = mb % 12;
        sh[t] = z[batch*ZDIM + t];
        __syncthreads();
        float acc = b0[t];
        for (int k = 0; k < ZDIM; k++) acc = fmaf(sh[k], w0[k*256 + t], acc);
        float v = (acc >= 0.f) ? acc : 0.2f*acc;
        __syncthreads(); sh[t] = v; __syncthreads();
        acc = b1[t];
        for (int k = 0; k < 256; k++) acc = fmaf(sh[k], w1[k*256 + t], acc);
        v = (acc >= 0.f) ? acc : 0.2f*acc;
        __syncthreads(); sh[t] = v; __syncthreads();
        if (t < 128) {
            int j = cb*128 + t;                     // covers [0,1536)
            float a = b2[j];
            for (int k = 0; k < 256; k++) a = fmaf(sh[k], w2[k*(FP_DIM*2) + j], a);
            if (j < FP_DIM) g_freqs[batch*FP_DIM + j] = a*15.0f + 30.0f;
            else            g_phases[batch*FP_DIM + (j - FP_DIM)] = a;
        }
    }
}

// ---------------- kernel 3/5: HMMA fused SIREN, 2 CTAs/SM, N-halved ---------
// (round-14 verified configuration — 401.2us baseline)
__global__ void __launch_bounds__(NTHR, 2)
siren_mma_kernel(int fine,
                 const float* __restrict__ fw, const float* __restrict__ fb,
                 const float* __restrict__ hb,
                 const float* __restrict__ ow, const float* __restrict__ ob) {
    extern __shared__ char smc[];
    uint32_t smb = smem_u32(smc);
    float* ptss = (float*)(smc + SM_PTS);
    float* frs  = (float*)(smc + SM_FR);
    float* phs  = (float*)(smc + SM_PH);
    float* bis  = (float*)(smc + SM_BI);
    float* fws  = (float*)(smc + SM_FW);
    float* fbs  = (float*)(smc + SM_FB);
    float* ows  = (float*)(smc + SM_OW);
    float* obs  = (float*)(smc + SM_OB);

    const float* pts  = fine ? g_points_f : g_points;
    float*       outr = fine ? g_rgbs_f   : g_rgbs_c;

    int tid = threadIdx.x;
    int wid = tid >> 5, lane = tid & 31;
    int m0 = blockIdx.x * MT;
    int batch = m0 / (HW*SS);

    for (int i = tid; i < BBUF/16; i += NTHR)
        cp16(smc + SM_B + i*16, g_wsplit + i*16);
    CP_COMMIT();

    {
        const float* frq = g_freqs  + batch*FP_DIM;
        const float* phq = g_phases + batch*FP_DIM;
        for (int i = tid; i < FP_DIM; i += NTHR) { frs[i] = frq[i]; phs[i] = phq[i]; }
        for (int i = tid; i < (NL-1)*HID; i += NTHR) bis[i] = hb[i];
        for (int i = tid; i < MT*3; i += NTHR) ptss[i] = pts[m0*3 + i];
        for (int i = tid; i < 384; i += NTHR) fws[i] = fw[i];
        if (tid < 128) fbs[tid] = fb[tid];
        for (int i = tid; i < 512; i += NTHR) ows[i] = ow[i];
        if (tid < 4) obs[tid] = ob[tid];
    }
    __syncthreads();

    uint32_t A0[8][4], A1[8][4];

    {
        int rr = lane >> 2;
        int mr0 = wid*16 + rr, mr1 = mr0 + 8;
        float p00 = ptss[mr0*3], p01 = ptss[mr0*3+1], p02 = ptss[mr0*3+2];
        float p10 = ptss[mr1*3], p11 = ptss[mr1*3+1], p12 = ptss[mr1*3+2];
#pragma unroll
        for (int j = 0; j < 16; j++) {
            int n = 8*j + 2*(lane & 3);
            float wa0 = fws[n],   wa1 = fws[128+n],   wa2 = fws[256+n];
            float wb0 = fws[n+1], wb1 = fws[128+n+1], wb2 = fws[256+n+1];
            float ba = fbs[n], bbv = fbs[n+1];
            float fa = frs[n], fbq = frs[n+1], pa = phs[n], pb = phs[n+1];
            float v0 = fast_sin(fa *(ba  + p00*wa0 + p01*wa1 + p02*wa2) + pa);
            float v1 = fast_sin(fbq*(bbv + p00*wb0 + p01*wb1 + p02*wb2) + pb);
            float v2 = fast_sin(fa *(ba  + p10*wa0 + p11*wa1 + p12*wa2) + pa);
            float v3 = fast_sin(fbq*(bbv + p10*wb0 + p11*wb1 + p12*wb2) + pb);
            int s = j >> 1, i0 = (j & 1)*2;
            pack2(v0, v1, A0[s][i0],   A1[s][i0]);
            pack2(v2, v3, A0[s][i0+1], A1[s][i0+1]);
        }
    }
    CP_WAIT0();
    __syncthreads();

    int tile = lane >> 3;
    uint32_t rowoff = (uint32_t)((((tile >> 1)*8 + (lane & 7))*WROW) + (tile & 1)*16);

#pragma unroll 1
    for (int l = 1; l < NL; l++) {
        uint32_t bbase = smb + SM_B;
        float acc[8][4];
        uint32_t Pa[16], Pb[16];
        float o0[4], o1[4];
        if (l == NL-1) {
#pragma unroll
            for (int q = 0; q < 4; q++) { o0[q] = 0.f; o1[q] = 0.f; }
        }

        // ================= half 0: n in [0,64), jq 0..1 =================
#pragma unroll
        for (int j = 0; j < 8; j++)
#pragma unroll
            for (int e = 0; e < 4; e++) acc[j][e] = 0.f;
#pragma unroll
        for (int s = 0; s < 8; s++) {
            uint32_t ad0 = bbase + s*32 + rowoff;
            uint32_t ad1 = ad0 + BSPL;
#pragma unroll
            for (int jq = 0; jq < 2; jq++) {
                uint32_t t0, t1, t2, t3, u0, u1, u2, u3;
                uint32_t v0, v1, v2, v3, w0, w1, w2, w3;
                LDMX4(t0, t1, t2, t3, ad0 + (2*jq)  *(16*WROW));
                LDMX4(u0, u1, u2, u3, ad0 + (2*jq+1)*(16*WROW));
                LDMX4(v0, v1, v2, v3, ad1 + (2*jq)  *(16*WROW));
                LDMX4(w0, w1, w2, w3, ad1 + (2*jq+1)*(16*WROW));
                float* c0 = acc[4*jq];
                float* c1 = acc[4*jq+1];
                float* c2 = acc[4*jq+2];
                float* c3 = acc[4*jq+3];
                MMA4(c0, A0[s][0], A0[s][1], A0[s][2], A0[s][3], t0, t1);
                MMA4(c1, A0[s][0], A0[s][1], A0[s][2], A0[s][3], t2, t3);
                MMA4(c2, A0[s][0], A0[s][1], A0[s][2], A0[s][3], u0, u1);
                MMA4(c3, A0[s][0], A0[s][1], A0[s][2], A0[s][3], u2, u3);
                MMA4(c0, A1[s][0], A1[s][1], A1[s][2], A1[s][3], t0, t1);
                MMA4(c1, A1[s][0], A1[s][1], A1[s][2], A1[s][3], t2, t3);
                MMA4(c2, A1[s][0], A1[s][1], A1[s][2], A1[s][3], u0, u1);
                MMA4(c3, A1[s][0], A1[s][1], A1[s][2], A1[s][3], u2, u3);
                MMA4(c0, A0[s][0], A0[s][1], A0[s][2], A0[s][3], v0, v1);
                MMA4(c1, A0[s][0], A0[s][1], A0[s][2], A0[s][3], v2, v3);
                MMA4(c2, A0[s][0], A0[s][1], A0[s][2], A0[s][3], w0, w1);
                MMA4(c3, A0[s][0], A0[s][1], A0[s][2], A0[s][3], w2, w3);
            }
        }

        // epilogue half 0 -> pending regs (A untouched; overlaps half-1 MMA)
        if (l < NL-1) {
#pragma unroll
            for (int j = 0; j < 8; j++) {
                int n = 8*j + 2*(lane & 3);
                float2 f  = *(const float2*)&frs[l*HID + n];
                float2 p  = *(const float2*)&phs[l*HID + n];
                float2 bb = *(const float2*)&bis[(l-1)*HID + n];
                float v0 = fast_sin(f.x*(acc[j][0] + bb.x) + p.x);
                float v1 = fast_sin(f.y*(acc[j][1] + bb.y) + p.y);
                float v2 = fast_sin(f.x*(acc[j][2] + bb.x) + p.x);
                float v3 = fast_sin(f.y*(acc[j][3] + bb.y) + p.y);
                int s = j >> 1, i0 = (j & 1)*2;
                pack2(v0, v1, Pa[s*4+i0],   Pb[s*4+i0]);
                pack2(v2, v3, Pa[s*4+i0+1], Pb[s*4+i0+1]);
            }
        } else {
#pragma unroll
            for (int j = 0; j < 8; j++) {
                int n = 8*j + 2*(lane & 3);
                float2 f  = *(const float2*)&frs[l*HID + n];
                float2 p  = *(const float2*)&phs[l*HID + n];
                float2 bb = *(const float2*)&bis[(l-1)*HID + n];
                float v0 = fast_sin(f.x*(acc[j][0] + bb.x) + p.x);
                float v1 = fast_sin(f.y*(acc[j][1] + bb.y) + p.y);
                float v2 = fast_sin(f.x*(acc[j][2] + bb.x) + p.x);
                float v3 = fast_sin(f.y*(acc[j][3] + bb.y) + p.y);
                float4 wA = *(const float4*)&ows[n*4];
                float4 wB = *(const float4*)&ows[(n+1)*4];
                o0[0] = fmaf(v0, wA.x, fmaf(v1, wB.x, o0[0]));
                o0[1] = fmaf(v0, wA.y, fmaf(v1, wB.y, o0[1]));
                o0[2] = fmaf(v0, wA.z, fmaf(v1, wB.z, o0[2]));
                o0[3] = fmaf(v0, wA.w, fmaf(v1, wB.w, o0[3]));
                o1[0] = fmaf(v2, wA.x, fmaf(v3, wB.x, o1[0]));
                o1[1] = fmaf(v2, wA.y, fmaf(v3, wB.y, o1[1]));
                o1[2] = fmaf(v2, wA.z, fmaf(v3, wB.z, o1[2]));
                o1[3] = fmaf(v2, wA.w, fmaf(v3, wB.w, o1[3]));
            }
        }

        // ================= half 1: n in [64,128), jq 2..3 =================
#pragma unroll
        for (int j = 0; j < 8; j++)
#pragma unroll
            for (int e = 0; e < 4; e++) acc[j][e] = 0.f;
#pragma unroll
        for (int s = 0; s < 8; s++) {
            uint32_t ad0 = bbase + s*32 + rowoff;
            uint32_t ad1 = ad0 + BSPL;
#pragma unroll
            for (int jq = 2; jq < 4; jq++) {
                uint32_t t0, t1, t2, t3, u0, u1, u2, u3;
                uint32_t v0, v1, v2, v3, w0, w1, w2, w3;
                LDMX4(t0, t1, t2, t3, ad0 + (2*jq)  *(16*WROW));
                LDMX4(u0, u1, u2, u3, ad0 + (2*jq+1)*(16*WROW));
                LDMX4(v0, v1, v2, v3, ad1 + (2*jq)  *(16*WROW));
                LDMX4(w0, w1, w2, w3, ad1 + (2*jq+1)*(16*WROW));
                float* c0 = acc[4*(jq-2)];
                float* c1 = acc[4*(jq-2)+1];
                float* c2 = acc[4*(jq-2)+2];
                float* c3 = acc[4*(jq-2)+3];
                MMA4(c0, A0[s][0], A0[s][1], A0[s][2], A0[s][3], t0, t1);
                MMA4(c1, A0[s][0], A0[s][1], A0[s][2], A0[s][3], t2, t3);
                MMA4(c2, A0[s][0], A0[s][1], A0[s][2], A0[s][3], u0, u1);
                MMA4(c3, A0[s][0], A0[s][1], A0[s][2], A0[s][3], u2, u3);
                MMA4(c0, A1[s][0], A1[s][1], A1[s][2], A1[s][3], t0, t1);
                MMA4(c1, A1[s][0], A1[s][1], A1[s][2], A1[s][3], t2, t3);
                MMA4(c2, A1[s][0], A1[s][1], A1[s][2], A1[s][3], u0, u1);
                MMA4(c3, A1[s][0], A1[s][1], A1[s][2], A1[s][3], u2, u3);
                MMA4(c0, A0[s][0], A0[s][1], A0[s][2], A0[s][3], v0, v1);
                MMA4(c1, A0[s][0], A0[s][1], A0[s][2], A0[s][3], v2, v3);
                MMA4(c2, A0[s][0], A0[s][1], A0[s][2], A0[s][3], w0, w1);
                MMA4(c3, A0[s][0], A0[s][1], A0[s][2], A0[s][3], w2, w3);
            }
        }
        __syncthreads();   // all B reads done before overwrite

        if (l < NL-1) {
            const char* src = g_wsplit + l*BBUF;
            for (int i = tid; i < BBUF/16; i += NTHR)
                cp16(smc + SM_B + i*16, src + i*16);
        }
        CP_COMMIT();

        if (l < NL-1) {
#pragma unroll
            for (int j = 8; j < 16; j++) {
                int n = 8*j + 2*(lane & 3);
                float2 f  = *(const float2*)&frs[l*HID + n];
                float2 p  = *(const float2*)&phs[l*HID + n];
                float2 bb = *(const float2*)&bis[(l-1)*HID + n];
                float v0 = fast_sin(f.x*(acc[j-8][0] + bb.x) + p.x);
                float v1 = fast_sin(f.y*(acc[j-8][1] + bb.y) + p.y);
                float v2 = fast_sin(f.x*(acc[j-8][2] + bb.x) + p.x);
                float v3 = fast_sin(f.y*(acc[j-8][3] + bb.y) + p.y);
                int s = j >> 1, i0 = (j & 1)*2;
                pack2(v0, v1, A0[s][i0],   A1[s][i0]);
                pack2(v2, v3, A0[s][i0+1], A1[s][i0+1]);
            }
#pragma unroll
            for (int s = 0; s < 4; s++)
#pragma unroll
                for (int i = 0; i < 4; i++) {
                    A0[s][i] = Pa[s*4+i];
                    A1[s][i] = Pb[s*4+i];
                }
        } else {
#pragma unroll
            for (int j = 8; j < 16; j++) {
                int n = 8*j + 2*(lane & 3);
                float2 f  = *(const float2*)&frs[l*HID + n];
                float2 p  = *(const float2*)&phs[l*HID + n];
                float2 bb = *(const float2*)&bis[(l-1)*HID + n];
                float v0 = fast_sin(f.x*(acc[j-8][0] + bb.x) + p.x);
                float v1 = fast_sin(f.y*(acc[j-8][1] + bb.y) + p.y);
                float v2 = fast_sin(f.x*(acc[j-8][2] + bb.x) + p.x);
                float v3 = fast_sin(f.y*(acc[j-8][3] + bb.y) + p.y);
                float4 wA = *(const float4*)&ows[n*4];
                float4 wB = *(const float4*)&ows[(n+1)*4];
                o0[0] = fmaf(v0, wA.x, fmaf(v1, wB.x, o0[0]));
                o0[1] = fmaf(v0, wA.y, fmaf(v1, wB.y, o0[1]));
                o0[2] = fmaf(v0, wA.z, fmaf(v1, wB.z, o0[2]));
                o0[3] = fmaf(v0, wA.w, fmaf(v1, wB.w, o0[3]));
                o1[0] = fmaf(v2, wA.x, fmaf(v3, wB.x, o1[0]));
                o1[1] = fmaf(v2, wA.y, fmaf(v3, wB.y, o1[1]));
                o1[2] = fmaf(v2, wA.z, fmaf(v3, wB.z, o1[2]));
                o1[3] = fmaf(v2, wA.w, fmaf(v3, wB.w, o1[3]));
            }
#pragma unroll
            for (int off = 1; off <= 2; off <<= 1) {
#pragma unroll
                for (int q = 0; q < 4; q++) {
                    o0[q] += __shfl_xor_sync(0xffffffffu, o0[q], off);
                    o1[q] += __shfl_xor_sync(0xffffffffu, o1[q], off);
                }
            }
            if ((lane & 3) == 0) {
                int rr = lane >> 2;
                int row0 = m0 + wid*16 + rr, row1 = row0 + 8;
                float a0 = o0[0] + obs[0], a1 = o0[1] + obs[1];
                float a2 = o0[2] + obs[2], a3 = o0[3] + obs[3];
                float b0 = o1[0] + obs[0], b1 = o1[1] + obs[1];
                float b2 = o1[2] + obs[2], b3 = o1[3] + obs[3];
                float4 q0 = make_float4(1.f/(1.f+expf(-a0)), 1.f/(1.f+expf(-a1)),
                                        1.f/(1.f+expf(-a2)), a3);
                float4 q1 = make_float4(1.f/(1.f+expf(-b0)), 1.f/(1.f+expf(-b1)),
                                        1.f/(1.f+expf(-b2)), b3);
                *(float4*)&outr[row0*4] = q0;
                *(float4*)&outr[row1*4] = q1;
            }
        }
        CP_WAIT0();
        __syncthreads();
    }
}

// ---------------- kernel 4: sampling, one thread per (ray, j) ----------------
__global__ void sample_kernel(const float* __restrict__ c2w,
                              uint32_t kq0, uint32_t kq1) {
    int gid = blockIdx.x * blockDim.x + threadIdx.x;
    if (gid >= NPTS) return;
    int ray = gid / SS;
    int b = ray / HW;
    int base = ray * SS;

    float z[SS], sg[SS];
    for (int s = 0; s < SS; s++) {
        z[s]  = g_zvals[base + s];
        sg[s] = g_rgbs_c[(base + s)*4 + 3];
    }
    float wgt[SS]; float T = 1.0f;
    for (int s = 0; s < SS; s++) {
        float d = (s < SS-1) ? (z[s+1] - z[s]) : 1e10f;
        float a = 1.0f - expf(-d * fmaxf(sg[s], 0.0f));
        wgt[s] = a * T;
        T *= (1.0f - a + 1e-10f);
    }
    float wq[SS-2]; float sum = 0.0f;
    for (int i = 0; i < SS-2; i++) { wq[i] = wgt[i+1] + 1e-5f; sum += wq[i]; }
    float cdf[SS-1]; cdf[0] = 0.0f; float c = 0.0f;
    for (int i = 0; i < SS-2; i++) { c += wq[i] / sum; cdf[i+1] = c; }
    float bins[SS-1];
    for (int i = 0; i < SS-1; i++) bins[i] = 0.5f * (z[i] + z[i+1]);

    float ox = c2w[b*16 + 3], oy = c2w[b*16 + 7], oz = c2w[b*16 + 11];
    float dx = g_dirs[ray*3+0], dy = g_dirs[ray*3+1], dz = g_dirs[ray*3+2];

    float u = jax_uniform(kq0, kq1, (uint32_t)gid);
    int ind = SS-1;
    for (int i = 0; i < SS-1; i++) { if (cdf[i] > u) { ind = i; break; } }
    int below = ind - 1; if (below < 0) below = 0; if (below > SS-2) below = SS-2;
    int above = (ind > SS-2) ? (SS-2) : ind;
    float clo = cdf[below], chi = cdf[above];
    float blo = bins[below], bhi = bins[above];
    float den = chi - clo; if (den < 1e-8f) den = 1.0f;
    float fz = blo + (u - clo) / den * (bhi - blo);
    g_finez[gid] = fz;
    g_points_f[gid*3 + 0] = ox + dx*fz;
    g_points_f[gid*3 + 1] = oy + dy*fz;
    g_points_f[gid*3 + 2] = oz + dz*fz;
}

// ---------------- kernel 6: merge-sort + final integration ------------------
// 64-thread blocks (4x CTA count for this latency-bound kernel); sort moves
// only (z, idx) pairs, rgba fetched in sorted order from L1/L2.
__global__ void final_kernel(float* __restrict__ out) {
    int ray = blockIdx.x * 64 + threadIdx.x;
    if (ray >= NRAYS) return;
    int b = ray / HW, r = ray % HW;
    int h = r / IMG, w = r % IMG;
    int base = ray * SS;

    float z[2*SS]; int id[2*SS];
    for (int s = 0; s < SS; s++) { z[s]    = g_finez[base+s]; id[s]    = s; }
    for (int s = 0; s < SS; s++) { z[SS+s] = g_zvals[base+s]; id[SS+s] = SS+s; }

    // stable insertion sort by z (fine entries precede coarse on ties)
    for (int i = 1; i < 2*SS; i++) {
        float kz = z[i]; int ki = id[i];
        int j = i - 1;
        while (j >= 0 && z[j] > kz) { z[j+1] = z[j]; id[j+1] = id[j]; j--; }
        z[j+1] = kz; id[j+1] = ki;
    }

    const float4* rf = reinterpret_cast<const float4*>(g_rgbs_f);
    const float4* rc = reinterpret_cast<const float4*>(g_rgbs_c);

    float T = 1.0f, R = 0.f, G = 0.f, Bc = 0.f, D = 0.f;
    for (int s = 0; s < 2*SS; s++) {
        int i = id[s];
        float4 cc = (i < SS) ? rf[base + i] : rc[base + (i - SS)];
        float d = (s < 2*SS-1) ? (z[s+1] - z[s]) : 1e10f;
        float a = 1.0f - expf(-d * fmaxf(cc.w, 0.0f));
        float wt = a * T;
        T *= (1.0f - a + 1e-10f);
        R += wt * cc.x; G += wt * cc.y; Bc += wt * cc.z; D += wt * z[s];
    }
    out[((b*3 + 0)*IMG + h)*IMG + w] = R  * 2.0f - 1.0f;
    out[((b*3 + 1)*IMG + h)*IMG + w] = G  * 2.0f - 1.0f;
    out[((b*3 + 2)*IMG + h)*IMG + w] = Bc * 2.0f - 1.0f;
    float x = -1.0f + w * (2.0f/63.0f);
    float y =  1.0f - h * (2.0f/63.0f);
    float n = sqrtf(x*x + y*y + ZC*ZC);
    out[BB*3*HW + ray] = D * (-(ZC/n));
}

// ---------------- launch ------------------------------------------------------
extern "C" void kernel_launch(void* const* d_in, const int* in_sizes, int n_in,
                              void* d_out, int out_size) {
    const float* z    = (const float*)d_in[0];
    const float* c2w  = (const float*)d_in[1];
    const float* mw0  = (const float*)d_in[2];
    const float* mb0  = (const float*)d_in[3];
    const float* mw1  = (const float*)d_in[4];
    const float* mb1  = (const float*)d_in[5];
    const float* mw2  = (const float*)d_in[6];
    const float* mb2  = (const float*)d_in[7];
    const float* fw   = (const float*)d_in[8];
    const float* fb   = (const float*)d_in[9];
    const float* hw_  = (const float*)d_in[10];
    const float* hb   = (const float*)d_in[11];
    const float* ow   = (const float*)d_in[12];
    const float* ob   = (const float*)d_in[13];
    float* out = (float*)d_out;

    uint32_t kp0, kp1, kq0, kq1;
    { uint32_t x0 = 0u, x1 = 0u; tf2x32(0u, 42u, x0, x1); kp0 = x0; kp1 = x1; }
    { uint32_t x0 = 0u, x1 = 1u; tf2x32(0u, 42u, x0, x1); kq0 = x0; kq1 = x1; }

    cudaFuncSetAttribute(siren_mma_kernel,
                         cudaFuncAttributeMaxDynamicSharedMemorySize, SM_TOTAL);

    prep_kernel<<<PREP_BLKS, 256>>>(z, c2w, mw0, mb0, mw1, mb1, mw2, mb2,
                                    hw_, kp0, kp1);
    siren_mma_kernel<<<NPTS/MT, NTHR, SM_TOTAL>>>(0, fw, fb, hb, ow, ob);
    sample_kernel<<<NPTS/256, 256>>>(c2w, kq0, kq1);
    siren_mma_kernel<<<NPTS/MT, NTHR, SM_TOTAL>>>(1, fw, fb, hb, ow, ob);
    final_kernel <<<NRAYS/64, 64>>>(out);
}